// round 2
// baseline (speedup 1.0000x reference)
#include <cuda_runtime.h>

#define D 64
#define MAXN 100000
#define MAXE 1250000
#define NLAYERS 3
#define BN_EPS 1e-5f

// ---------------- static device scratch (no allocations allowed) -------------
__device__ int   g_deg[MAXN];
__device__ int   g_rowptr[MAXN + 1];
__device__ int   g_cursor[MAXN];
__device__ int   g_blocksums[256];
__device__ int   g_srcsorted[MAXE];
__device__ __align__(16) float g_h[(size_t)MAXN * D];
__device__ __align__(16) float g_x[(size_t)MAXN * D];
__device__ float g_colsum[D];
__device__ float g_colsq[D];
__device__ float g_scale[D];
__device__ float g_shift[D];

// ---------------- CSR build --------------------------------------------------
__global__ void k_zero_deg(int N) {
    int i = blockIdx.x * blockDim.x + threadIdx.x;
    if (i < N) g_deg[i] = 0;
}

__global__ void k_hist(const int* __restrict__ ei, int E) {
    int e = blockIdx.x * blockDim.x + threadIdx.x;
    if (e < E) atomicAdd(&g_deg[ei[E + e]], 1);
}

// chunk = 1024 elements per block (256 threads x 4)
__global__ void k_scan1(int N) {
    __shared__ int sh[256];
    int tid = threadIdx.x;
    int base = blockIdx.x * 1024 + tid * 4;
    int v0 = (base + 0 < N) ? g_deg[base + 0] : 0;
    int v1 = (base + 1 < N) ? g_deg[base + 1] : 0;
    int v2 = (base + 2 < N) ? g_deg[base + 2] : 0;
    int v3 = (base + 3 < N) ? g_deg[base + 3] : 0;
    int t0 = v0, t1 = t0 + v1, t2 = t1 + v2, t3 = t2 + v3;
    sh[tid] = t3;
    __syncthreads();
    for (int off = 1; off < 256; off <<= 1) {
        int add = (tid >= off) ? sh[tid - off] : 0;
        __syncthreads();
        sh[tid] += add;
        __syncthreads();
    }
    int excl = sh[tid] - t3;
    if (base + 0 < N) g_rowptr[base + 1] = excl + t0;
    if (base + 1 < N) g_rowptr[base + 2] = excl + t1;
    if (base + 2 < N) g_rowptr[base + 3] = excl + t2;
    if (base + 3 < N) g_rowptr[base + 4] = excl + t3;
    if (tid == 255) g_blocksums[blockIdx.x] = sh[255];
}

__global__ void k_scan2(int NB) {
    if (threadIdx.x == 0) {
        int run = 0;
        for (int b = 0; b < NB; b++) { int t = g_blocksums[b]; g_blocksums[b] = run; run += t; }
    }
}

__global__ void k_scan3(int N) {
    int base = blockIdx.x * 1024 + threadIdx.x * 4;
    int off = g_blocksums[blockIdx.x];
#pragma unroll
    for (int i = 0; i < 4; i++)
        if (base + i < N) g_rowptr[base + 1 + i] += off;
    if (blockIdx.x == 0 && threadIdx.x == 0) g_rowptr[0] = 0;
}

__global__ void k_copy_cursor(int N) {
    int i = blockIdx.x * blockDim.x + threadIdx.x;
    if (i < N) g_cursor[i] = g_rowptr[i];
}

__global__ void k_bucket(const int* __restrict__ ei, int E) {
    int e = blockIdx.x * blockDim.x + threadIdx.x;
    if (e < E) {
        int d = ei[E + e];
        int pos = atomicAdd(&g_cursor[d], 1);
        g_srcsorted[pos] = ei[e];
    }
}

// ---------------- per-layer fused aggregate + dual GEMM + BN stats ----------
__global__ void k_zero_stats() {
    int t = threadIdx.x;
    if (t < D) { g_colsum[t] = 0.f; g_colsq[t] = 0.f; }
}

__global__ void __launch_bounds__(256) k_layer(
    const float* __restrict__ x0, int use_global,
    const float* __restrict__ Wrel, const float* __restrict__ brel,
    const float* __restrict__ Wroot, int N)
{
    __shared__ float s_wa[D * D];
    __shared__ float s_wb[D * D];
    __shared__ float s_sum[D];
    __shared__ float s_sq[D];
    const float* __restrict__ x_in = use_global ? (const float*)g_x : x0;

    int tid = threadIdx.x;
    for (int i = tid; i < D * D; i += 256) { s_wa[i] = Wrel[i]; s_wb[i] = Wroot[i]; }
    if (tid < D) { s_sum[tid] = 0.f; s_sq[tid] = 0.f; }
    __syncthreads();

    int lane = tid & 31;
    int wid = (blockIdx.x * blockDim.x + tid) >> 5;
    int nwarps = (gridDim.x * blockDim.x) >> 5;

    float ps0 = 0.f, pq0 = 0.f, ps1 = 0.f, pq1 = 0.f;

    for (int i = wid; i < N; i += nwarps) {
        const float* xr = x_in + (size_t)i * D;
        float xv0 = xr[lane], xv1 = xr[lane + 32];

        float m0 = 0.f, m1 = 0.f;
        int rs = g_rowptr[i], re = g_rowptr[i + 1];
        for (int base = rs; base < re; base += 32) {
            int j = base + lane;
            int sj = (j < re) ? g_srcsorted[j] : 0;
            int cnt = min(32, re - base);
            for (int u = 0; u < cnt; u++) {
                int s = __shfl_sync(0xffffffffu, sj, u);
                const float* xs = x_in + (size_t)s * D;
                m0 += xs[lane];
                m1 += xs[lane + 32];
            }
        }

        float acc0 = brel[lane], acc1 = brel[lane + 32];
#pragma unroll
        for (int k = 0; k < D; k++) {
            float mk = __shfl_sync(0xffffffffu, (k < 32) ? m0 : m1, k & 31);
            float xk = __shfl_sync(0xffffffffu, (k < 32) ? xv0 : xv1, k & 31);
            acc0 = fmaf(mk, s_wa[k * D + lane], fmaf(xk, s_wb[k * D + lane], acc0));
            acc1 = fmaf(mk, s_wa[k * D + lane + 32], fmaf(xk, s_wb[k * D + lane + 32], acc1));
        }
        g_h[(size_t)i * D + lane] = acc0;
        g_h[(size_t)i * D + lane + 32] = acc1;
        ps0 += acc0; pq0 += acc0 * acc0;
        ps1 += acc1; pq1 += acc1 * acc1;
    }

    atomicAdd(&s_sum[lane], ps0);       atomicAdd(&s_sq[lane], pq0);
    atomicAdd(&s_sum[lane + 32], ps1);  atomicAdd(&s_sq[lane + 32], pq1);
    __syncthreads();
    if (tid < D) {
        atomicAdd(&g_colsum[tid], s_sum[tid]);
        atomicAdd(&g_colsq[tid],  s_sq[tid]);
    }
}

__global__ void k_bn(const float* __restrict__ gamma, const float* __restrict__ beta, float invN) {
    int t = threadIdx.x;
    if (t < D) {
        float mean = g_colsum[t] * invN;
        float var  = g_colsq[t] * invN - mean * mean;
        var = var < 0.f ? 0.f : var;
        float sc = gamma[t] * rsqrtf(var + BN_EPS);
        g_scale[t] = sc;
        g_shift[t] = beta[t] - mean * sc;
    }
}

__global__ void k_apply(int total4) {
    int i = blockIdx.x * blockDim.x + threadIdx.x;
    if (i < total4) {
        int c = (i & 15) * 4;
        float4 v = ((const float4*)g_h)[i];
        float4 o;
        o.x = fmaxf(0.f, fmaf(v.x, g_scale[c + 0], g_shift[c + 0]));
        o.y = fmaxf(0.f, fmaf(v.y, g_scale[c + 1], g_shift[c + 1]));
        o.z = fmaxf(0.f, fmaf(v.z, g_scale[c + 2], g_shift[c + 2]));
        o.w = fmaxf(0.f, fmaf(v.w, g_scale[c + 3], g_shift[c + 3]));
        ((float4*)g_x)[i] = o;
    }
}

// ---------------- pooling + classifier (one block per graph) ----------------
__global__ void k_pool(const int* __restrict__ batch, int N,
                       const float* __restrict__ Wcls, const float* __restrict__ bcls,
                       float* __restrict__ out)
{
    __shared__ float s_pool[D];
    int g = blockIdx.x, tid = threadIdx.x;

    int lo = 0, hi = N;
    while (lo < hi) { int mid = (lo + hi) >> 1; if (batch[mid] < g) lo = mid + 1; else hi = mid; }
    int start = lo;
    hi = N;
    while (lo < hi) { int mid = (lo + hi) >> 1; if (batch[mid] < g + 1) lo = mid + 1; else hi = mid; }
    int end = lo;

    if (tid < D) s_pool[tid] = 0.f;
    __syncthreads();

    int col = tid & 63, rg = tid >> 6;
    float p = 0.f;
    for (int r = start + rg; r < end; r += 4) p += g_x[(size_t)r * D + col];
    atomicAdd(&s_pool[col], p);
    __syncthreads();

    float cnt = (float)(end - start);
    float denom = cnt > 1.f ? cnt : 1.f;
    if (tid < D) s_pool[tid] /= denom;
    __syncthreads();

    if (tid < 10) {
        float acc = bcls[tid];
#pragma unroll
        for (int d = 0; d < D; d++) acc = fmaf(s_pool[d], Wcls[d * 10 + tid], acc);
        out[g * 10 + tid] = acc;
    }
}

// ---------------- launch -----------------------------------------------------
extern "C" void kernel_launch(void* const* d_in, const int* in_sizes, int n_in,
                              void* d_out, int out_size)
{
    const float* x     = (const float*)d_in[0];
    const int*   ei    = (const int*)d_in[1];
    const int*   batch = (const int*)d_in[2];
    const float* Wrel  = (const float*)d_in[3];
    const float* brel  = (const float*)d_in[4];
    const float* Wroot = (const float*)d_in[5];
    const float* gamma = (const float*)d_in[6];
    const float* beta  = (const float*)d_in[7];
    const float* Wcls  = (const float*)d_in[8];
    const float* bcls  = (const float*)d_in[9];
    float* out = (float*)d_out;

    int N = in_sizes[0] / D;
    int E = in_sizes[1] / 2;
    int G = out_size / 10;
    int NB = (N + 1023) / 1024;
    float invN = 1.f / (float)N;

    // CSR build (reused by all layers)
    k_zero_deg<<<(N + 255) / 256, 256>>>(N);
    k_hist<<<(E + 255) / 256, 256>>>(ei, E);
    k_scan1<<<NB, 256>>>(N);
    k_scan2<<<1, 32>>>(NB);
    k_scan3<<<NB, 256>>>(N);
    k_copy_cursor<<<(N + 255) / 256, 256>>>(N);
    k_bucket<<<(E + 255) / 256, 256>>>(ei, E);

    for (int l = 0; l < NLAYERS; l++) {
        k_zero_stats<<<1, 64>>>();
        k_layer<<<1184, 256>>>(x, (l > 0) ? 1 : 0,
                               Wrel + (size_t)l * D * D, brel + (size_t)l * D,
                               Wroot + (size_t)l * D * D, N);
        k_bn<<<1, 64>>>(gamma + (size_t)l * D, beta + (size_t)l * D, invN);
        k_apply<<<(N * 16 + 255) / 256, 256>>>(N * 16);
    }

    k_pool<<<G, 256>>>(batch, N, Wcls, bcls, out);
}